// round 17
// baseline (speedup 1.0000x reference)
#include <cuda_runtime.h>
#include <cuda_bf16.h>
#include <cstdint>

// ---------------- problem constants ----------------
#define CLASSES   100000
#define CPAD      100096               // 782*128 padded classes
#define KDIM      512
#define BATCHN    512
#define NCTA      782                  // class tiles of 128
#define PPAD      784                  // padded partial stride per batch row
#define NCHUNK    8                    // K chunks of 64
#define EXPK      92.33248261689366f   // 64 * log2(e)

static constexpr float C_COS_M = 0.8775825618903728f;   // cos(0.5)
static constexpr float C_SIN_M = 0.479425538604203f;    // sin(0.5)
static constexpr float C_TH    = -0.8775825618903728f;  // cos(pi-0.5)
static constexpr float C_MM    = 0.23971276930210156f;  // sin(pi-0.5)*0.5

// ---------------- device scratch (static: no allocations allowed) ----------------
__device__ __nv_bfloat16 g_xn[BATCHN * KDIM];          // normalized x, bf16
__device__ __nv_bfloat16 g_wb[(size_t)CPAD * KDIM];    // normalized w, bf16 (zero-padded)
__device__ float g_partials[(size_t)BATCHN * PPAD];    // per (b, class-tile) exp sums
__device__ float g_cost[BATCHN];                       // cosine at target class
__device__ float g_lossb[BATCHN];                      // per-sample loss
__device__ int   g_tgt[BATCHN];                        // targets as int32 (dtype-robust)
__device__ unsigned g_ctr;                             // last-block-done counter
__device__ int   g_flag[NCTA];                         // per-ctile convert counters

// ---------------- helpers ----------------
__device__ __forceinline__ uint32_t smem_u32(const void* p) {
    uint32_t a;
    asm("{ .reg .u64 t; cvta.to.shared.u64 t, %1; cvt.u32.u64 %0, t; }" : "=r"(a) : "l"(p));
    return a;
}
__device__ __forceinline__ void cp_async16_cg(uint32_t saddr, const void* gptr) {
    asm volatile("cp.async.cg.shared.global [%0], [%1], 16;"
                 :: "r"(saddr), "l"(__cvta_generic_to_global(gptr)));
}
__device__ __forceinline__ void cp_async16_ca(uint32_t saddr, const void* gptr) {
    asm volatile("cp.async.ca.shared.global [%0], [%1], 16;"
                 :: "r"(saddr), "l"(__cvta_generic_to_global(gptr)));
}
__device__ __forceinline__ void cp_commit() {
    asm volatile("cp.async.commit_group;" ::: "memory");
}
template <int N>
__device__ __forceinline__ void cp_wait() {
    asm volatile("cp.async.wait_group %0;" :: "n"(N) : "memory");
}
__device__ __forceinline__ void ldsm_x4(uint32_t* r, uint32_t addr) {
    asm volatile("ldmatrix.sync.aligned.m8n8.x4.shared.b16 {%0,%1,%2,%3}, [%4];"
                 : "=r"(r[0]), "=r"(r[1]), "=r"(r[2]), "=r"(r[3]) : "r"(addr));
}
__device__ __forceinline__ void mma_bf16(float* d, const uint32_t* a, uint32_t b0, uint32_t b1) {
    asm volatile(
        "mma.sync.aligned.m16n8k16.row.col.f32.bf16.bf16.f32 "
        "{%0,%1,%2,%3}, {%4,%5,%6,%7}, {%8,%9}, {%0,%1,%2,%3};"
        : "+f"(d[0]), "+f"(d[1]), "+f"(d[2]), "+f"(d[3])
        : "r"(a[0]), "r"(a[1]), "r"(a[2]), "r"(a[3]), "r"(b0), "r"(b1));
}
__device__ __forceinline__ uint32_t pack_bf16x2(float a, float b) {
    __nv_bfloat162 p = __floats2bfloat162_rn(a, b);
    return *(uint32_t*)&p;
}
__device__ __forceinline__ float ex2_approx(float x) {   // bare MUFU.EX2
    float r;
    asm("ex2.approx.f32 %0, %1;" : "=f"(r) : "f"(x));
    return r;
}

// ---------------- dynamic smem layout for GEMM (3-stage) ----------------
#define SM_STAGE  32768
#define SM_RSUM   98304     // 128*2 f32 = 1024
#define SM_TGT    99328     // 128 int = 512
#define SMEM_DYN  (99840 + 1024)

// ======================= K1: normalize x -> bf16 (+ targets, ctr, flags) ===============
__global__ void __launch_bounds__(128) k_norm_x(const float* __restrict__ x,
                                                const int* __restrict__ t32) {
    __shared__ float red[4];
    __shared__ int nz;
    int b = blockIdx.x;
    int tid = threadIdx.x;

    // zero per-ctile flags (graph-replay safe)
    if (tid == 0) {
        g_flag[b] = 0;
        if (b < NCTA - 512) g_flag[512 + b] = 0;
        if (b == 0) g_ctr = 0u;
    }

    int tv[4];
    if (b == 0) {
        if (tid == 0) nz = 0;
        #pragma unroll
        for (int i = 0; i < 4; i++) tv[i] = t32[tid + i * 128];
    }

    float4 v = *(const float4*)(x + (size_t)b * KDIM + tid * 4);
    float sq = v.x * v.x + v.y * v.y + v.z * v.z + v.w * v.w;
    #pragma unroll
    for (int m = 16; m >= 1; m >>= 1) sq += __shfl_xor_sync(0xffffffffu, sq, m);
    if ((tid & 31) == 0) red[tid >> 5] = sq;
    __syncthreads();

    if (b == 0) {
        #pragma unroll
        for (int i = 0; i < 4; i++) {
            int idx = tid + i * 128;
            if ((idx & 1) && tv[i] != 0) atomicAdd(&nz, 1);
        }
    }
    __syncthreads();

    float inv = 1.0f / fmaxf(sqrtf(red[0] + red[1] + red[2] + red[3]), 1e-12f);
    uint2 pk;
    pk.x = pack_bf16x2(v.x * inv, v.y * inv);
    pk.y = pack_bf16x2(v.z * inv, v.w * inv);
    *(uint2*)(&g_xn[(size_t)b * KDIM + tid * 4]) = pk;

    if (b == 0) {
        bool is64 = (nz == 0);
        #pragma unroll
        for (int i = 0; i < 4; i++) {
            int idx = tid + i * 128;
            g_tgt[idx] = is64 ? t32[2 * idx] : t32[idx];
        }
    }
}

// ======================= K2: HMMA GEMM + in-CTA w-normalization + partial LSE ==========
// Each of the 4 sibling CTAs of a class tile converts ITS quarter (32 rows) of
// the f32 weights into normalized bf16 g_wb, then all 4 sync on g_flag[ctile].
// The GEMM pipeline then reads the (L2-hot) bf16 tile as before.
__global__ void __launch_bounds__(256, 2) k_gemm(const float* __restrict__ w) {
    extern __shared__ char dsm[];
    uint32_t base = smem_u32(dsm);
    uint32_t A = (base + 1023u) & ~1023u;
    char* SA = dsm + (A - base);

    int tid = threadIdx.x;
    int wid = tid >> 5;
    int lid = tid & 31;
    int warpM = wid >> 1;          // 0..3  (32 batch rows each)
    int warpN = wid & 1;           // 0..1  (64 class cols each)

    int ctile = blockIdx.x >> 2;
    int btile = blockIdx.x & 3;
    int cls0 = ctile * 128;
    int b0 = btile * 128;

    int* tgt_s = (int*)(SA + SM_TGT);
    if (tid < 128) tgt_s[tid] = g_tgt[b0 + tid];

    // ---------------- convert quarter: rows [btile*32, btile*32+32) of the tile ------
    {
        int crow = tid >> 3;                  // 0..31 (row within quarter)
        int cl = tid & 7;                     // 8 threads per row
        int wrow = cls0 + btile * 32 + crow;  // global class row
        bool ok = (wrow < CLASSES);
        const float4* src = (const float4*)(w + (size_t)wrow * KDIM) + cl * 16;

        float sq = 0.0f;
        if (ok) {
            #pragma unroll
            for (int i = 0; i < 16; i++) {
                float4 t = src[i];
                sq += t.x * t.x + t.y * t.y + t.z * t.z + t.w * t.w;
            }
        }
        #pragma unroll
        for (int m = 4; m >= 1; m >>= 1) sq += __shfl_xor_sync(0xffffffffu, sq, m);
        float inv = 1.0f / fmaxf(sqrtf(sq), 1e-12f);

        uint4* dst = (uint4*)(g_wb + (size_t)wrow * KDIM + cl * 64);
        if (ok) {
            #pragma unroll
            for (int i = 0; i < 8; i++) {      // reload (L1-hot) + convert + store
                float4 a = src[2 * i];
                float4 c = src[2 * i + 1];
                uint4 u;
                u.x = pack_bf16x2(a.x * inv, a.y * inv);
                u.y = pack_bf16x2(a.z * inv, a.w * inv);
                u.z = pack_bf16x2(c.x * inv, c.y * inv);
                u.w = pack_bf16x2(c.z * inv, c.w * inv);
                dst[i] = u;
            }
        } else {
            uint4 z = make_uint4(0u, 0u, 0u, 0u);
            #pragma unroll
            for (int i = 0; i < 8; i++) dst[i] = z;
        }
    }
    __syncthreads();                  // all quarter stores issued by this CTA
    if (tid == 0) {
        __threadfence();              // release: g_wb writes visible before arrive
        atomicAdd(&g_flag[ctile], 1);
        int v;
        do {
            asm volatile("ld.acquire.gpu.b32 %0, [%1];"
                         : "=r"(v) : "l"(&g_flag[ctile]) : "memory");
        } while (v < 4);
    }
    __syncthreads();                  // tile complete: safe to read all 128 rows

    // ---------------- standard R15 pipeline ----------------
    int lrow = tid >> 3;                   // 0..31
    int lcol = (tid & 7) * 16;
    uint32_t st_sw = A + (uint32_t)(lrow * 128 + (lcol ^ ((lrow & 7) << 4)));
    const char* pA = (const char*)g_xn + (size_t)b0 * 1024 + lrow * 1024 + (tid & 7) * 16;
    const char* pB = (const char*)g_wb + (size_t)cls0 * 1024 + lrow * 1024 + (tid & 7) * 16;

    auto ld = [&](int kc, int st) {
        #pragma unroll
        for (int i = 0; i < 4; i++)
            cp_async16_ca(st_sw + st * SM_STAGE + i * 4096, pA + i * 32768 + kc * 128);
        #pragma unroll
        for (int i = 0; i < 4; i++)
            cp_async16_cg(st_sw + st * SM_STAGE + 16384 + i * 4096, pB + i * 32768 + kc * 128);
        cp_commit();
    };

    int lr = lid & 15;
    int lh = (lid >> 4) * 16;
    uint32_t pat = (uint32_t)((lr & 7) << 4);
    uint32_t ko[4];
    #pragma unroll
    for (int ks = 0; ks < 4; ks++) ko[ks] = (uint32_t)((ks * 32 + lh) ^ pat);
    uint32_t ldA = A + (uint32_t)((warpM * 32 + lr) * 128);
    uint32_t ldB = A + 16384u + (uint32_t)((warpN * 64 + lr) * 128);

    float acc[2][8][4];
    #pragma unroll
    for (int i = 0; i < 2; i++)
        #pragma unroll
        for (int j = 0; j < 8; j++)
            #pragma unroll
            for (int q = 0; q < 4; q++) acc[i][j][q] = 0.0f;

    ld(0, 0);
    ld(1, 1);

    uint32_t bfr[2][4][4];
    uint32_t afr[2][2][4];

    #pragma unroll
    for (int kc = 0; kc < NCHUNK; kc++) {
        if (kc < NCHUNK - 1) cp_wait<1>();
        else                 cp_wait<0>();
        __syncthreads();      // stage kc visible; stage (kc+2)%3 reusable

        if (kc + 2 < NCHUNK) ld(kc + 2, (kc + 2) % 3);

        const uint32_t sOff = (uint32_t)((kc % 3) * SM_STAGE);

        #pragma unroll
        for (int nt4 = 0; nt4 < 4; nt4++)
            ldsm_x4(bfr[0][nt4], ldB + sOff + nt4 * 2048 + ko[0]);
        #pragma unroll
        for (int mt = 0; mt < 2; mt++)
            ldsm_x4(afr[0][mt], ldA + sOff + mt * 2048 + ko[0]);

        #pragma unroll
        for (int ks = 0; ks < 4; ks++) {
            int cur = ks & 1;
            int nxt = cur ^ 1;
            if (ks < 3) {
                #pragma unroll
                for (int nt4 = 0; nt4 < 4; nt4++)
                    ldsm_x4(bfr[nxt][nt4], ldB + sOff + nt4 * 2048 + ko[ks + 1]);
                #pragma unroll
                for (int mt = 0; mt < 2; mt++)
                    ldsm_x4(afr[nxt][mt], ldA + sOff + mt * 2048 + ko[ks + 1]);
            }
            #pragma unroll
            for (int mt = 0; mt < 2; mt++) {
                #pragma unroll
                for (int nt4 = 0; nt4 < 4; nt4++) {
                    mma_bf16(acc[mt][nt4 * 2 + 0], afr[cur][mt], bfr[cur][nt4][0], bfr[cur][nt4][2]);
                    mma_bf16(acc[mt][nt4 * 2 + 1], afr[cur][mt], bfr[cur][nt4][1], bfr[cur][nt4][3]);
                }
            }
        }
    }

    // ---------------- epilogue: branch-free partial LSE (target included) ----------------
    float* rsum = (float*)(SA + SM_RSUM);
    int g = lid >> 2;
    int tg = lid & 3;

    float rs[4] = {0.f, 0.f, 0.f, 0.f};
    #pragma unroll
    for (int mt = 0; mt < 2; mt++) {
        int rlo = warpM * 32 + mt * 16 + g;
        int rhi = rlo + 8;
        int tlo = tgt_s[rlo];
        int thi = tgt_s[rhi];
        #pragma unroll
        for (int nt = 0; nt < 8; nt++) {
            int colb = warpN * 64 + nt * 8 + tg * 2;
            #pragma unroll
            for (int q = 0; q < 4; q++) {
                int cls = cls0 + colb + (q & 1);
                float cosv = acc[mt][nt][q];
                int t = (q < 2) ? tlo : thi;
                if (cls == t) g_cost[b0 + ((q < 2) ? rlo : rhi)] = cosv;
                rs[mt * 2 + (q >> 1)] += ex2_approx(fmaf(EXPK, cosv, -EXPK));
            }
        }
    }
    #pragma unroll
    for (int i = 0; i < 4; i++) {
        rs[i] += __shfl_xor_sync(0xffffffffu, rs[i], 1);
        rs[i] += __shfl_xor_sync(0xffffffffu, rs[i], 2);
    }
    if (tg == 0) {
        #pragma unroll
        for (int mt = 0; mt < 2; mt++) {
            int rlo = warpM * 32 + mt * 16 + g;
            rsum[rlo * 2 + warpN] = rs[mt * 2 + 0];
            rsum[(rlo + 8) * 2 + warpN] = rs[mt * 2 + 1];
        }
    }
    __syncthreads();
    if (tid < 128) {
        g_partials[(size_t)(b0 + tid) * PPAD + ctile] = rsum[tid * 2] + rsum[tid * 2 + 1];
    }
}

// ======================= K3: reduce + margin + final mean (fused) =======================
__global__ void __launch_bounds__(256) k_reduce_b(float* __restrict__ out) {
    __shared__ unsigned last;
    int tid = threadIdx.x;
    int wid = tid >> 5;
    int lane = tid & 31;
    int b = blockIdx.x * 8 + wid;

    float acc = 0.0f;
    for (int i = lane; i < NCTA; i += 32)
        acc += g_partials[(size_t)b * PPAD + i];
    #pragma unroll
    for (int m = 16; m >= 1; m >>= 1) acc += __shfl_xor_sync(0xffffffffu, acc, m);
    if (lane == 0) {
        float ct = g_cost[b];
        acc -= ex2_approx(fmaf(EXPK, ct, -EXPK));   // bit-identical to gemm's added term
        float st = sqrtf(fmaxf(1.0f - ct * ct, 0.0f));
        float phi = ct * C_COS_M - st * C_SIN_M;
        phi = (ct > C_TH) ? phi : (ct - C_MM);
        acc += ex2_approx(fmaf(EXPK, phi, -EXPK));
        g_lossb[b] = 64.0f + logf(acc) - 64.0f * phi;
    }
    __threadfence();
    __syncthreads();
    if (tid == 0) last = atomicAdd(&g_ctr, 1u);
    __syncthreads();
    if (last == 63u) {
        __shared__ float red[8];
        float v = g_lossb[tid] + g_lossb[tid + 256];
        #pragma unroll
        for (int m = 16; m >= 1; m >>= 1) v += __shfl_xor_sync(0xffffffffu, v, m);
        if (lane == 0) red[wid] = v;
        __syncthreads();
        if (tid == 0) {
            float s = 0.0f;
            #pragma unroll
            for (int i = 0; i < 8; i++) s += red[i];
            out[0] = s * (1.0f / (float)BATCHN);
        }
    }
}

// ======================= launch =======================
extern "C" void kernel_launch(void* const* d_in, const int* in_sizes, int n_in,
                              void* d_out, int out_size) {
    const float* x = (const float*)d_in[0];
    const float* w = (const float*)d_in[1];
    const int* tgt_raw = (const int*)d_in[2];
    float* out = (float*)d_out;

    cudaFuncSetAttribute(k_gemm, cudaFuncAttributeMaxDynamicSharedMemorySize, SMEM_DYN);

    k_norm_x<<<BATCHN, 128>>>(x, tgt_raw);
    k_gemm<<<NCTA * 4, 256, SMEM_DYN>>>(w);
    k_reduce_b<<<64, 256>>>(out);
}